// round 3
// baseline (speedup 1.0000x reference)
#include <cuda_runtime.h>
#include <cuda_bf16.h>
#include <cstdint>
#include <cstddef>

#define DEV __device__ __forceinline__

static constexpr int Bdim = 4096;
static constexpr int Ddim = 2048;
static constexpr int Hlay = 3;

static constexpr int BM = 128;
static constexpr int BN = 128;
static constexpr int BK = 32;               // 32 bf16 = 64B/row, padded to 80B
static constexpr int NCH = Ddim / BK;       // 64
static constexpr int GT = 512;              // 16 warps, 4(m) x 4(n)

static constexpr int ROWB = 80;             // padded row bytes (conflict-free ldmatrix)
static constexpr int TILEB = 128 * ROWB;    // 10240 per tile
static constexpr int STAGEB = 4 * TILEB;    // A_hi, A_lo, B_hi, B_lo = 40960
static constexpr int NSTAGE = 4;
static constexpr int SMEM_TOTAL = NSTAGE * STAGEB;  // 163840

__device__ __nv_bfloat16 g_w_hi[(size_t)Hlay * Ddim * Ddim];
__device__ __nv_bfloat16 g_w_lo[(size_t)Hlay * Ddim * Ddim];
__device__ __nv_bfloat16 g_act_hi[2][(size_t)Bdim * Ddim];
__device__ __nv_bfloat16 g_act_lo[2][(size_t)Bdim * Ddim];
__device__ float g_bias[Hlay * Ddim];
__device__ float g_wo[Ddim];
__device__ float g_bo;

DEV uint32_t smem_u32(const void* p) { return (uint32_t)__cvta_generic_to_shared(p); }

DEV void cp16(uint32_t s, const void* g) {
    asm volatile("cp.async.cg.shared.global [%0], [%1], 16;\n"
                 :: "r"(s), "l"(__cvta_generic_to_global(g)) : "memory");
}

DEV void ldsm4(uint32_t* r, uint32_t addr) {
    asm volatile("ldmatrix.sync.aligned.m8n8.x4.shared.b16 {%0,%1,%2,%3}, [%4];"
                 : "=r"(r[0]), "=r"(r[1]), "=r"(r[2]), "=r"(r[3]) : "r"(addr));
}

DEV void mma_bf16(float* c, const uint32_t* a, const uint32_t* b) {
    asm volatile(
        "mma.sync.aligned.m16n8k16.row.col.f32.bf16.bf16.f32 "
        "{%0,%1,%2,%3}, {%4,%5,%6,%7}, {%8,%9}, {%0,%1,%2,%3};\n"
        : "+f"(c[0]), "+f"(c[1]), "+f"(c[2]), "+f"(c[3])
        : "r"(a[0]), "r"(a[1]), "r"(a[2]), "r"(a[3]), "r"(b[0]), "r"(b[1]));
}

DEV float softplusf(float x) { return fmaxf(x, 0.0f) + log1pf(expf(-fabsf(x))); }

DEV void split_pack(float a, float b, uint32_t& hi, uint32_t& lo) {
    __nv_bfloat16 ha = __float2bfloat16(a), hb = __float2bfloat16(b);
    float ra = a - __bfloat162float(ha), rb = b - __bfloat162float(hb);
    hi = (uint32_t)__bfloat16_as_ushort(ha) | ((uint32_t)__bfloat16_as_ushort(hb) << 16);
    __nv_bfloat16 la = __float2bfloat16(ra), lb = __float2bfloat16(rb);
    lo = (uint32_t)__bfloat16_as_ushort(la) | ((uint32_t)__bfloat16_as_ushort(lb) << 16);
}

// ---------------- prep ----------------
__global__ void prep_w_kernel(const float4* __restrict__ mu, const float4* __restrict__ rho,
                              const float4* __restrict__ eps) {
    const size_t n4 = (size_t)Hlay * Ddim * Ddim / 4;
    for (size_t i = (size_t)blockIdx.x * blockDim.x + threadIdx.x; i < n4;
         i += (size_t)gridDim.x * blockDim.x) {
        float4 m = mu[i], r = rho[i], e = eps[i];
        uint32_t h0, l0, h1, l1;
        split_pack(fmaf(e.x, softplusf(r.x), m.x), fmaf(e.y, softplusf(r.y), m.y), h0, l0);
        split_pack(fmaf(e.z, softplusf(r.z), m.z), fmaf(e.w, softplusf(r.w), m.w), h1, l1);
        *reinterpret_cast<uint2*>(g_w_hi + i * 4) = make_uint2(h0, h1);
        *reinterpret_cast<uint2*>(g_w_lo + i * 4) = make_uint2(l0, l1);
    }
}

__global__ void prep_x_kernel(const float4* __restrict__ x) {
    const size_t n4 = (size_t)Bdim * Ddim / 4;
    for (size_t i = (size_t)blockIdx.x * blockDim.x + threadIdx.x; i < n4;
         i += (size_t)gridDim.x * blockDim.x) {
        float4 v = x[i];
        uint32_t h0, l0, h1, l1;
        split_pack(v.x, v.y, h0, l0);
        split_pack(v.z, v.w, h1, l1);
        *reinterpret_cast<uint2*>(&g_act_hi[0][i * 4]) = make_uint2(h0, h1);
        *reinterpret_cast<uint2*>(&g_act_lo[0][i * 4]) = make_uint2(l0, l1);
    }
}

__global__ void prep_small_kernel(const float* __restrict__ bmu, const float* __restrict__ brho,
                                  const float* __restrict__ ebh,
                                  const float* __restrict__ wmo, const float* __restrict__ wro,
                                  const float* __restrict__ ewo,
                                  const float* __restrict__ bmo, const float* __restrict__ bro,
                                  const float* __restrict__ ebo) {
    int i = blockIdx.x * blockDim.x + threadIdx.x;
    if (i < Hlay * Ddim) {
        g_bias[i] = fmaf(ebh[i], softplusf(brho[i]), bmu[i]);
    } else if (i < Hlay * Ddim + Ddim) {
        int j = i - Hlay * Ddim;
        g_wo[j] = fmaf(ewo[j], softplusf(wro[j]), wmo[j]);
    } else if (i == Hlay * Ddim + Ddim) {
        g_bo = fmaf(ebo[0], softplusf(bro[0]), bmo[0]);
    }
}

// ---------------- GEMM: C = relu(A @ W^T + b), bf16x3 split, mma.sync ----------------
__global__ void __launch_bounds__(GT, 1)
gemm_kernel(int layer, int inbuf, int outbuf) {
    extern __shared__ char smraw[];
    const uint32_t sb = smem_u32(smraw);
    const int tid = threadIdx.x;
    const int lane = tid & 31, w = tid >> 5;
    const int wm = w & 3, wn = w >> 2;
    const int m0 = blockIdx.x * BM, n0 = blockIdx.y * BN;

    const __nv_bfloat16* __restrict__ a_hi = g_act_hi[inbuf];
    const __nv_bfloat16* __restrict__ a_lo = g_act_lo[inbuf];
    const __nv_bfloat16* __restrict__ w_hi = g_w_hi + (size_t)layer * Ddim * Ddim;
    const __nv_bfloat16* __restrict__ w_lo = g_w_lo + (size_t)layer * Ddim * Ddim;
    const float* __restrict__ bias = g_bias + layer * Ddim;
    __nv_bfloat16* __restrict__ o_hi = g_act_hi[outbuf];
    __nv_bfloat16* __restrict__ o_lo = g_act_lo[outbuf];

    // per-thread load coords: 512 thr x (1 chunk each of A_hi/A_lo/B_hi/B_lo)
    const int lrow = tid >> 2, lc = tid & 3;
    const uint32_t lso = (uint32_t)(lrow * ROWB + lc * 16);

    auto load_stage = [&](int slot, int kc) {
        const uint32_t st = sb + slot * STAGEB;
        const size_t ga = (size_t)(m0 + lrow) * Ddim + kc * BK + lc * 8;
        const size_t gb = (size_t)(n0 + lrow) * Ddim + kc * BK + lc * 8;
        cp16(st + lso, a_hi + ga);
        cp16(st + TILEB + lso, a_lo + ga);
        cp16(st + 2 * TILEB + lso, w_hi + gb);
        cp16(st + 3 * TILEB + lso, w_lo + gb);
        asm volatile("cp.async.commit_group;" ::: "memory");
    };

    float acc[2][4][4];
#pragma unroll
    for (int mt = 0; mt < 2; mt++)
#pragma unroll
        for (int nt = 0; nt < 4; nt++)
#pragma unroll
            for (int j = 0; j < 4; j++) acc[mt][nt][j] = 0.0f;

    // ldmatrix lane offsets
    const uint32_t aoff = (uint32_t)((lane & 15) * ROWB + (lane >> 4) * 16);
    const uint32_t boff = (uint32_t)((((lane & 7) + ((lane >> 4) << 3)) * ROWB)
                                     + (((lane >> 3) & 1) * 16));

    load_stage(0, 0);
    load_stage(1, 1);
    load_stage(2, 2);

    for (int kc = 0; kc < NCH; kc++) {
        if (kc <= NCH - 3)      asm volatile("cp.async.wait_group 2;" ::: "memory");
        else if (kc == NCH - 2) asm volatile("cp.async.wait_group 1;" ::: "memory");
        else                    asm volatile("cp.async.wait_group 0;" ::: "memory");
        __syncthreads();
        if (kc + 3 < NCH) load_stage((kc + 3) & 3, kc + 3);

        const uint32_t st = sb + (kc & 3) * STAGEB;
        const uint32_t ab = st + (uint32_t)(wm * 32 * ROWB) + aoff;
        const uint32_t bb = st + 2 * TILEB + (uint32_t)(wn * 32 * ROWB) + boff;
#pragma unroll
        for (int ks = 0; ks < 2; ks++) {
            uint32_t ah[2][4], al[2][4], bh[2][4], bl[2][4];
#pragma unroll
            for (int mt = 0; mt < 2; mt++) {
                uint32_t a = ab + mt * 16 * ROWB + ks * 32;
                ldsm4(ah[mt], a);
                ldsm4(al[mt], a + TILEB);
            }
#pragma unroll
            for (int np = 0; np < 2; np++) {
                uint32_t b = bb + np * 16 * ROWB + ks * 32;
                ldsm4(bh[np], b);
                ldsm4(bl[np], b + TILEB);
            }
#pragma unroll
            for (int mt = 0; mt < 2; mt++)
#pragma unroll
                for (int np = 0; np < 2; np++)
#pragma unroll
                    for (int hf = 0; hf < 2; hf++) {
                        float* c = acc[mt][np * 2 + hf];
                        mma_bf16(c, ah[mt], &bh[np][2 * hf]);
                        mma_bf16(c, al[mt], &bh[np][2 * hf]);
                        mma_bf16(c, ah[mt], &bl[np][2 * hf]);
                    }
        }
    }

    // epilogue: bias + relu + bf16 hi/lo split
    const int mrow = m0 + wm * 32 + (lane >> 2);
    const int ncol0 = n0 + wn * 32 + 2 * (lane & 3);
#pragma unroll
    for (int mt = 0; mt < 2; mt++) {
#pragma unroll
        for (int nt = 0; nt < 4; nt++) {
            const int n = ncol0 + nt * 8;
            const float b0 = __ldg(bias + n), b1 = __ldg(bias + n + 1);
#pragma unroll
            for (int hf = 0; hf < 2; hf++) {
                const int m = mrow + mt * 16 + hf * 8;
                float y0 = fmaxf(acc[mt][nt][2 * hf] + b0, 0.0f);
                float y1 = fmaxf(acc[mt][nt][2 * hf + 1] + b1, 0.0f);
                uint32_t hi, lo;
                split_pack(y0, y1, hi, lo);
                *reinterpret_cast<uint32_t*>(o_hi + (size_t)m * Ddim + n) = hi;
                *reinterpret_cast<uint32_t*>(o_lo + (size_t)m * Ddim + n) = lo;
            }
        }
    }
}

// ---------------- output layer: N=1 dot ----------------
__global__ void out_kernel(float* __restrict__ out) {
    const int row = blockIdx.x * 8 + (threadIdx.x >> 5);
    const int lid = threadIdx.x & 31;
    const __nv_bfloat16* hi = g_act_hi[1] + (size_t)row * Ddim;
    const __nv_bfloat16* lo = g_act_lo[1] + (size_t)row * Ddim;
    float s = 0.0f;
    for (int j = lid; j < Ddim; j += 32)
        s += (__bfloat162float(__ldg(hi + j)) + __bfloat162float(__ldg(lo + j))) * __ldg(&g_wo[j]);
#pragma unroll
    for (int o = 16; o; o >>= 1) s += __shfl_xor_sync(0xFFFFFFFFu, s, o);
    if (lid == 0) out[row] = s + g_bo;
}

extern "C" void kernel_launch(void* const* d_in, const int* in_sizes, int n_in,
                              void* d_out, int out_size) {
    (void)in_sizes; (void)n_in; (void)out_size;
    prep_w_kernel<<<4096, 256>>>((const float4*)d_in[1], (const float4*)d_in[2],
                                 (const float4*)d_in[9]);
    prep_x_kernel<<<2048, 256>>>((const float4*)d_in[0]);
    prep_small_kernel<<<33, 256>>>((const float*)d_in[3], (const float*)d_in[4],
                                   (const float*)d_in[10],
                                   (const float*)d_in[5], (const float*)d_in[6],
                                   (const float*)d_in[11],
                                   (const float*)d_in[7], (const float*)d_in[8],
                                   (const float*)d_in[12]);
    cudaFuncSetAttribute(gemm_kernel, cudaFuncAttributeMaxDynamicSharedMemorySize, SMEM_TOTAL);
    dim3 grid(Bdim / BM, Ddim / BN);
    gemm_kernel<<<grid, GT, SMEM_TOTAL>>>(0, 0, 1);
    gemm_kernel<<<grid, GT, SMEM_TOTAL>>>(1, 1, 0);
    gemm_kernel<<<grid, GT, SMEM_TOTAL>>>(2, 0, 1);
    out_kernel<<<Bdim / 8, 256>>>((float*)d_out);
}

// round 4
// speedup vs baseline: 1.0359x; 1.0359x over previous
#include <cuda_runtime.h>
#include <cuda_bf16.h>
#include <cstdint>
#include <cstddef>

#define DEV __device__ __forceinline__

static constexpr int Bdim = 4096;
static constexpr int Ddim = 2048;
static constexpr int Hlay = 3;

static constexpr int BM = 128;
static constexpr int BN = 128;
static constexpr int BK = 32;               // 32 bf16 = 64B/row, padded to 80B
static constexpr int NCH = Ddim / BK;       // 64
static constexpr int GT = 256;              // 8 warps: 4(m) x 2(n), warp tile 32x64

static constexpr int ROWB = 80;             // padded row bytes (conflict-free ldmatrix)
static constexpr int TILEB = 128 * ROWB;    // 10240 per tile
static constexpr int STAGEB = 4 * TILEB;    // A_hi, A_lo, B_hi, B_lo = 40960
static constexpr int NSTAGE = 2;
static constexpr int SMEM_TOTAL = NSTAGE * STAGEB;  // 81920 -> 2 CTAs/SM

__device__ __nv_bfloat16 g_w_hi[(size_t)Hlay * Ddim * Ddim];
__device__ __nv_bfloat16 g_w_lo[(size_t)Hlay * Ddim * Ddim];
__device__ __nv_bfloat16 g_act_hi[2][(size_t)Bdim * Ddim];
__device__ __nv_bfloat16 g_act_lo[2][(size_t)Bdim * Ddim];
__device__ float g_bias[Hlay * Ddim];
__device__ float g_wo[Ddim];
__device__ float g_bo;

DEV uint32_t smem_u32(const void* p) { return (uint32_t)__cvta_generic_to_shared(p); }

DEV void cp16(uint32_t s, const void* g) {
    asm volatile("cp.async.cg.shared.global [%0], [%1], 16;\n"
                 :: "r"(s), "l"(__cvta_generic_to_global(g)) : "memory");
}

DEV void ldsm4(uint32_t* r, uint32_t addr) {
    asm volatile("ldmatrix.sync.aligned.m8n8.x4.shared.b16 {%0,%1,%2,%3}, [%4];"
                 : "=r"(r[0]), "=r"(r[1]), "=r"(r[2]), "=r"(r[3]) : "r"(addr));
}

DEV void mma_bf16(float* c, const uint32_t* a, const uint32_t* b) {
    asm volatile(
        "mma.sync.aligned.m16n8k16.row.col.f32.bf16.bf16.f32 "
        "{%0,%1,%2,%3}, {%4,%5,%6,%7}, {%8,%9}, {%0,%1,%2,%3};\n"
        : "+f"(c[0]), "+f"(c[1]), "+f"(c[2]), "+f"(c[3])
        : "r"(a[0]), "r"(a[1]), "r"(a[2]), "r"(a[3]), "r"(b[0]), "r"(b[1]));
}

DEV float softplusf(float x) { return fmaxf(x, 0.0f) + log1pf(expf(-fabsf(x))); }

DEV void split_pack(float a, float b, uint32_t& hi, uint32_t& lo) {
    __nv_bfloat16 ha = __float2bfloat16(a), hb = __float2bfloat16(b);
    float ra = a - __bfloat162float(ha), rb = b - __bfloat162float(hb);
    hi = (uint32_t)__bfloat16_as_ushort(ha) | ((uint32_t)__bfloat16_as_ushort(hb) << 16);
    __nv_bfloat16 la = __float2bfloat16(ra), lb = __float2bfloat16(rb);
    lo = (uint32_t)__bfloat16_as_ushort(la) | ((uint32_t)__bfloat16_as_ushort(lb) << 16);
}

// ---------------- prep ----------------
__global__ void prep_w_kernel(const float4* __restrict__ mu, const float4* __restrict__ rho,
                              const float4* __restrict__ eps) {
    const size_t n4 = (size_t)Hlay * Ddim * Ddim / 4;
    for (size_t i = (size_t)blockIdx.x * blockDim.x + threadIdx.x; i < n4;
         i += (size_t)gridDim.x * blockDim.x) {
        float4 m = mu[i], r = rho[i], e = eps[i];
        uint32_t h0, l0, h1, l1;
        split_pack(fmaf(e.x, softplusf(r.x), m.x), fmaf(e.y, softplusf(r.y), m.y), h0, l0);
        split_pack(fmaf(e.z, softplusf(r.z), m.z), fmaf(e.w, softplusf(r.w), m.w), h1, l1);
        *reinterpret_cast<uint2*>(g_w_hi + i * 4) = make_uint2(h0, h1);
        *reinterpret_cast<uint2*>(g_w_lo + i * 4) = make_uint2(l0, l1);
    }
}

__global__ void prep_x_kernel(const float4* __restrict__ x) {
    const size_t n4 = (size_t)Bdim * Ddim / 4;
    for (size_t i = (size_t)blockIdx.x * blockDim.x + threadIdx.x; i < n4;
         i += (size_t)gridDim.x * blockDim.x) {
        float4 v = x[i];
        uint32_t h0, l0, h1, l1;
        split_pack(v.x, v.y, h0, l0);
        split_pack(v.z, v.w, h1, l1);
        *reinterpret_cast<uint2*>(&g_act_hi[0][i * 4]) = make_uint2(h0, h1);
        *reinterpret_cast<uint2*>(&g_act_lo[0][i * 4]) = make_uint2(l0, l1);
    }
}

__global__ void prep_small_kernel(const float* __restrict__ bmu, const float* __restrict__ brho,
                                  const float* __restrict__ ebh,
                                  const float* __restrict__ wmo, const float* __restrict__ wro,
                                  const float* __restrict__ ewo,
                                  const float* __restrict__ bmo, const float* __restrict__ bro,
                                  const float* __restrict__ ebo) {
    int i = blockIdx.x * blockDim.x + threadIdx.x;
    if (i < Hlay * Ddim) {
        g_bias[i] = fmaf(ebh[i], softplusf(brho[i]), bmu[i]);
    } else if (i < Hlay * Ddim + Ddim) {
        int j = i - Hlay * Ddim;
        g_wo[j] = fmaf(ewo[j], softplusf(wro[j]), wmo[j]);
    } else if (i == Hlay * Ddim + Ddim) {
        g_bo = fmaf(ebo[0], softplusf(bro[0]), bmo[0]);
    }
}

// ---------------- GEMM: C = relu(A @ W^T + b), bf16x3 split, mma.sync ----------------
__global__ void __launch_bounds__(GT, 2)
gemm_kernel(int layer, int inbuf, int outbuf) {
    extern __shared__ char smraw[];
    const uint32_t sb = smem_u32(smraw);
    const int tid = threadIdx.x;
    const int lane = tid & 31, w = tid >> 5;
    const int wm = w & 3, wn = w >> 2;          // warp tile: 32 (m) x 64 (n)
    const int m0 = blockIdx.x * BM, n0 = blockIdx.y * BN;

    const __nv_bfloat16* __restrict__ a_hi = g_act_hi[inbuf];
    const __nv_bfloat16* __restrict__ a_lo = g_act_lo[inbuf];
    const __nv_bfloat16* __restrict__ w_hi = g_w_hi + (size_t)layer * Ddim * Ddim;
    const __nv_bfloat16* __restrict__ w_lo = g_w_lo + (size_t)layer * Ddim * Ddim;
    const float* __restrict__ bias = g_bias + layer * Ddim;
    __nv_bfloat16* __restrict__ o_hi = g_act_hi[outbuf];
    __nv_bfloat16* __restrict__ o_lo = g_act_lo[outbuf];

    // loads: 256 thr, each thread = 1 row-half (32B) of each of the 4 tiles
    const int lrow = tid >> 1, lc0 = (tid & 1) * 2;
    const uint32_t lso = (uint32_t)(lrow * ROWB + lc0 * 16);

    auto load_stage = [&](int slot, int kc) {
        const uint32_t st = sb + slot * STAGEB;
        const size_t ga = (size_t)(m0 + lrow) * Ddim + kc * BK + lc0 * 8;
        const size_t gb = (size_t)(n0 + lrow) * Ddim + kc * BK + lc0 * 8;
        cp16(st + lso, a_hi + ga);
        cp16(st + lso + 16, a_hi + ga + 8);
        cp16(st + TILEB + lso, a_lo + ga);
        cp16(st + TILEB + lso + 16, a_lo + ga + 8);
        cp16(st + 2 * TILEB + lso, w_hi + gb);
        cp16(st + 2 * TILEB + lso + 16, w_hi + gb + 8);
        cp16(st + 3 * TILEB + lso, w_lo + gb);
        cp16(st + 3 * TILEB + lso + 16, w_lo + gb + 8);
        asm volatile("cp.async.commit_group;" ::: "memory");
    };

    float acc[2][8][4];
#pragma unroll
    for (int mt = 0; mt < 2; mt++)
#pragma unroll
        for (int nt = 0; nt < 8; nt++)
#pragma unroll
            for (int j = 0; j < 4; j++) acc[mt][nt][j] = 0.0f;

    const uint32_t aoff = (uint32_t)((lane & 15) * ROWB + (lane >> 4) * 16);
    const uint32_t boff = (uint32_t)((((lane & 7) + ((lane >> 4) << 3)) * ROWB)
                                     + (((lane >> 3) & 1) * 16));

    load_stage(0, 0);

    for (int kc = 0; kc < NCH; kc++) {
        const int s = kc & 1;
        asm volatile("cp.async.wait_group 0;" ::: "memory");
        __syncthreads();
        if (kc + 1 < NCH) load_stage(s ^ 1, kc + 1);

        const uint32_t st = sb + s * STAGEB;
        const uint32_t ab = st + (uint32_t)(wm * 32 * ROWB) + aoff;
        const uint32_t bb = st + 2 * TILEB + (uint32_t)(wn * 64 * ROWB) + boff;
#pragma unroll
        for (int ks = 0; ks < 2; ks++) {
            uint32_t ah[2][4], al[2][4];
#pragma unroll
            for (int mt = 0; mt < 2; mt++) {
                uint32_t a = ab + mt * 16 * ROWB + ks * 32;
                ldsm4(ah[mt], a);
                ldsm4(al[mt], a + TILEB);
            }
#pragma unroll
            for (int np = 0; np < 4; np++) {
                uint32_t bh[4], bl[4];
                uint32_t b = bb + np * 16 * ROWB + ks * 32;
                ldsm4(bh, b);
                ldsm4(bl, b + TILEB);
#pragma unroll
                for (int mt = 0; mt < 2; mt++)
#pragma unroll
                    for (int hf = 0; hf < 2; hf++) {
                        float* c = acc[mt][np * 2 + hf];
                        mma_bf16(c, ah[mt], &bh[2 * hf]);
                        mma_bf16(c, al[mt], &bh[2 * hf]);
                        mma_bf16(c, ah[mt], &bl[2 * hf]);
                    }
            }
        }
    }

    // epilogue: bias + relu + bf16 hi/lo split
    const int mrow = m0 + wm * 32 + (lane >> 2);
    const int ncol0 = n0 + wn * 64 + 2 * (lane & 3);
#pragma unroll
    for (int mt = 0; mt < 2; mt++) {
#pragma unroll
        for (int nt = 0; nt < 8; nt++) {
            const int n = ncol0 + nt * 8;
            const float b0 = __ldg(bias + n), b1 = __ldg(bias + n + 1);
#pragma unroll
            for (int hf = 0; hf < 2; hf++) {
                const int m = mrow + mt * 16 + hf * 8;
                float y0 = fmaxf(acc[mt][nt][2 * hf] + b0, 0.0f);
                float y1 = fmaxf(acc[mt][nt][2 * hf + 1] + b1, 0.0f);
                uint32_t hi, lo;
                split_pack(y0, y1, hi, lo);
                *reinterpret_cast<uint32_t*>(o_hi + (size_t)m * Ddim + n) = hi;
                *reinterpret_cast<uint32_t*>(o_lo + (size_t)m * Ddim + n) = lo;
            }
        }
    }
}

// ---------------- output layer: N=1 dot ----------------
__global__ void out_kernel(float* __restrict__ out) {
    const int row = blockIdx.x * 8 + (threadIdx.x >> 5);
    const int lid = threadIdx.x & 31;
    const __nv_bfloat16* hi = g_act_hi[1] + (size_t)row * Ddim;
    const __nv_bfloat16* lo = g_act_lo[1] + (size_t)row * Ddim;
    float s = 0.0f;
    for (int j = lid; j < Ddim; j += 32)
        s += (__bfloat162float(__ldg(hi + j)) + __bfloat162float(__ldg(lo + j))) * __ldg(&g_wo[j]);
#pragma unroll
    for (int o = 16; o; o >>= 1) s += __shfl_xor_sync(0xFFFFFFFFu, s, o);
    if (lid == 0) out[row] = s + g_bo;
}

extern "C" void kernel_launch(void* const* d_in, const int* in_sizes, int n_in,
                              void* d_out, int out_size) {
    (void)in_sizes; (void)n_in; (void)out_size;
    prep_w_kernel<<<4096, 256>>>((const float4*)d_in[1], (const float4*)d_in[2],
                                 (const float4*)d_in[9]);
    prep_x_kernel<<<2048, 256>>>((const float4*)d_in[0]);
    prep_small_kernel<<<33, 256>>>((const float*)d_in[3], (const float*)d_in[4],
                                   (const float*)d_in[10],
                                   (const float*)d_in[5], (const float*)d_in[6],
                                   (const float*)d_in[11],
                                   (const float*)d_in[7], (const float*)d_in[8],
                                   (const float*)d_in[12]);
    cudaFuncSetAttribute(gemm_kernel, cudaFuncAttributeMaxDynamicSharedMemorySize, SMEM_TOTAL);
    dim3 grid(Bdim / BM, Ddim / BN);
    gemm_kernel<<<grid, GT, SMEM_TOTAL>>>(0, 0, 1);
    gemm_kernel<<<grid, GT, SMEM_TOTAL>>>(1, 1, 0);
    gemm_kernel<<<grid, GT, SMEM_TOTAL>>>(2, 0, 1);
    out_kernel<<<Bdim / 8, 256>>>((float*)d_out);
}

// round 5
// speedup vs baseline: 1.4740x; 1.4229x over previous
#include <cuda_runtime.h>
#include <cuda_bf16.h>
#include <cuda_fp16.h>
#include <cstdint>
#include <cstddef>

#define DEV __device__ __forceinline__

static constexpr int Bdim = 4096;
static constexpr int Ddim = 2048;
static constexpr int Hlay = 3;

static constexpr int BM = 128;
static constexpr int BN = 128;
static constexpr int BK = 32;               // 32 fp16 = 64B/row, padded to 80B
static constexpr int NCH = Ddim / BK;       // 64
static constexpr int GT = 256;              // 8 warps: 4(m) x 2(n), warp tile 32x64

static constexpr int ROWB = 80;             // padded row bytes (conflict-free ldmatrix)
static constexpr int TILEB = 128 * ROWB;    // 10240 per tile
static constexpr int STAGEB = 3 * TILEB;    // A_hi, A_lo, W = 30720
static constexpr int NSTAGE = 3;
static constexpr int SMEM_TOTAL = NSTAGE * STAGEB;  // 92160 -> 2 CTAs/SM

__device__ __half g_w[(size_t)Hlay * Ddim * Ddim];
__device__ __half g_act_hi[2][(size_t)Bdim * Ddim];
__device__ __half g_act_lo[2][(size_t)Bdim * Ddim];
__device__ float g_bias[Hlay * Ddim];
__device__ float g_wo[Ddim];
__device__ float g_bo;

DEV uint32_t smem_u32(const void* p) { return (uint32_t)__cvta_generic_to_shared(p); }

DEV void cp16(uint32_t s, const void* g) {
    asm volatile("cp.async.cg.shared.global [%0], [%1], 16;\n"
                 :: "r"(s), "l"(__cvta_generic_to_global(g)) : "memory");
}

DEV void ldsm4(uint32_t* r, uint32_t addr) {
    asm volatile("ldmatrix.sync.aligned.m8n8.x4.shared.b16 {%0,%1,%2,%3}, [%4];"
                 : "=r"(r[0]), "=r"(r[1]), "=r"(r[2]), "=r"(r[3]) : "r"(addr));
}

DEV void mma_f16(float* c, const uint32_t* a, const uint32_t* b) {
    asm volatile(
        "mma.sync.aligned.m16n8k16.row.col.f32.f16.f16.f32 "
        "{%0,%1,%2,%3}, {%4,%5,%6,%7}, {%8,%9}, {%0,%1,%2,%3};\n"
        : "+f"(c[0]), "+f"(c[1]), "+f"(c[2]), "+f"(c[3])
        : "r"(a[0]), "r"(a[1]), "r"(a[2]), "r"(a[3]), "r"(b[0]), "r"(b[1]));
}

DEV float softplusf(float x) { return fmaxf(x, 0.0f) + log1pf(expf(-fabsf(x))); }

// fp16 hi/lo split of two floats, packed as half2 words
DEV void split_pack_h(float a, float b, uint32_t& hi, uint32_t& lo) {
    __half ha = __float2half_rn(a), hb = __float2half_rn(b);
    float ra = a - __half2float(ha), rb = b - __half2float(hb);
    __half la = __float2half_rn(ra), lb = __float2half_rn(rb);
    hi = (uint32_t)__half_as_ushort(ha) | ((uint32_t)__half_as_ushort(hb) << 16);
    lo = (uint32_t)__half_as_ushort(la) | ((uint32_t)__half_as_ushort(lb) << 16);
}

// ---------------- prep ----------------
__global__ void prep_w_kernel(const float4* __restrict__ mu, const float4* __restrict__ rho,
                              const float4* __restrict__ eps) {
    const size_t n4 = (size_t)Hlay * Ddim * Ddim / 4;
    for (size_t i = (size_t)blockIdx.x * blockDim.x + threadIdx.x; i < n4;
         i += (size_t)gridDim.x * blockDim.x) {
        float4 m = mu[i], r = rho[i], e = eps[i];
        float w0 = fmaf(e.x, softplusf(r.x), m.x);
        float w1 = fmaf(e.y, softplusf(r.y), m.y);
        float w2 = fmaf(e.z, softplusf(r.z), m.z);
        float w3 = fmaf(e.w, softplusf(r.w), m.w);
        uint32_t p0 = (uint32_t)__half_as_ushort(__float2half_rn(w0))
                    | ((uint32_t)__half_as_ushort(__float2half_rn(w1)) << 16);
        uint32_t p1 = (uint32_t)__half_as_ushort(__float2half_rn(w2))
                    | ((uint32_t)__half_as_ushort(__float2half_rn(w3)) << 16);
        *reinterpret_cast<uint2*>(g_w + i * 4) = make_uint2(p0, p1);
    }
}

__global__ void prep_x_kernel(const float4* __restrict__ x) {
    const size_t n4 = (size_t)Bdim * Ddim / 4;
    for (size_t i = (size_t)blockIdx.x * blockDim.x + threadIdx.x; i < n4;
         i += (size_t)gridDim.x * blockDim.x) {
        float4 v = x[i];
        uint32_t h0, l0, h1, l1;
        split_pack_h(v.x, v.y, h0, l0);
        split_pack_h(v.z, v.w, h1, l1);
        *reinterpret_cast<uint2*>(&g_act_hi[0][i * 4]) = make_uint2(h0, h1);
        *reinterpret_cast<uint2*>(&g_act_lo[0][i * 4]) = make_uint2(l0, l1);
    }
}

__global__ void prep_small_kernel(const float* __restrict__ bmu, const float* __restrict__ brho,
                                  const float* __restrict__ ebh,
                                  const float* __restrict__ wmo, const float* __restrict__ wro,
                                  const float* __restrict__ ewo,
                                  const float* __restrict__ bmo, const float* __restrict__ bro,
                                  const float* __restrict__ ebo) {
    int i = blockIdx.x * blockDim.x + threadIdx.x;
    if (i < Hlay * Ddim) {
        g_bias[i] = fmaf(ebh[i], softplusf(brho[i]), bmu[i]);
    } else if (i < Hlay * Ddim + Ddim) {
        int j = i - Hlay * Ddim;
        g_wo[j] = fmaf(ewo[j], softplusf(wro[j]), wmo[j]);
    } else if (i == Hlay * Ddim + Ddim) {
        g_bo = fmaf(ebo[0], softplusf(bro[0]), bmo[0]);
    }
}

// ---------------- GEMM: C = relu(A @ W^T + b), fp16 2-term split ----------------
__global__ void __launch_bounds__(GT, 2)
gemm_kernel(int layer, int inbuf, int outbuf) {
    extern __shared__ char smraw[];
    const uint32_t sb = smem_u32(smraw);
    const int tid = threadIdx.x;
    const int lane = tid & 31, w = tid >> 5;
    const int wm = w & 3, wn = w >> 2;          // warp tile: 32 (m) x 64 (n)
    const int m0 = blockIdx.x * BM, n0 = blockIdx.y * BN;

    const __half* __restrict__ a_hi = g_act_hi[inbuf];
    const __half* __restrict__ a_lo = g_act_lo[inbuf];
    const __half* __restrict__ wgt = g_w + (size_t)layer * Ddim * Ddim;
    const float* __restrict__ bias = g_bias + layer * Ddim;
    __half* __restrict__ o_hi = g_act_hi[outbuf];
    __half* __restrict__ o_lo = g_act_lo[outbuf];

    // loads: 256 thr; per tile each thread covers 1 row-half (2 x 16B)
    const int lrow = tid >> 1, lc0 = (tid & 1) * 2;
    const uint32_t lso = (uint32_t)(lrow * ROWB + lc0 * 16);

    auto load_stage = [&](int slot, int kc) {
        const uint32_t st = sb + slot * STAGEB;
        const size_t ga = (size_t)(m0 + lrow) * Ddim + kc * BK + lc0 * 8;
        const size_t gb = (size_t)(n0 + lrow) * Ddim + kc * BK + lc0 * 8;
        cp16(st + lso, a_hi + ga);
        cp16(st + lso + 16, a_hi + ga + 8);
        cp16(st + TILEB + lso, a_lo + ga);
        cp16(st + TILEB + lso + 16, a_lo + ga + 8);
        cp16(st + 2 * TILEB + lso, wgt + gb);
        cp16(st + 2 * TILEB + lso + 16, wgt + gb + 8);
        asm volatile("cp.async.commit_group;" ::: "memory");
    };

    float acc[2][8][4];
#pragma unroll
    for (int mt = 0; mt < 2; mt++)
#pragma unroll
        for (int nt = 0; nt < 8; nt++)
#pragma unroll
            for (int j = 0; j < 4; j++) acc[mt][nt][j] = 0.0f;

    const uint32_t aoff = (uint32_t)((lane & 15) * ROWB + (lane >> 4) * 16);
    const uint32_t boff = (uint32_t)((((lane & 7) + ((lane >> 4) << 3)) * ROWB)
                                     + (((lane >> 3) & 1) * 16));

    load_stage(0, 0);
    load_stage(1, 1);

    int slot = 0;
    for (int kc = 0; kc < NCH; kc++) {
        if (kc == NCH - 1) asm volatile("cp.async.wait_group 0;" ::: "memory");
        else               asm volatile("cp.async.wait_group 1;" ::: "memory");
        __syncthreads();
        if (kc + 2 < NCH) {
            int ns = slot + 2; if (ns >= NSTAGE) ns -= NSTAGE;
            load_stage(ns, kc + 2);
        }

        const uint32_t st = sb + slot * STAGEB;
        const uint32_t ab = st + (uint32_t)(wm * 32 * ROWB) + aoff;
        const uint32_t bb = st + 2 * TILEB + (uint32_t)(wn * 64 * ROWB) + boff;
#pragma unroll
        for (int ks = 0; ks < 2; ks++) {
            uint32_t ah[2][4], al[2][4];
#pragma unroll
            for (int mt = 0; mt < 2; mt++) {
                uint32_t a = ab + mt * 16 * ROWB + ks * 32;
                ldsm4(ah[mt], a);
                ldsm4(al[mt], a + TILEB);
            }
#pragma unroll
            for (int np = 0; np < 4; np++) {
                uint32_t bh[4];
                ldsm4(bh, bb + np * 16 * ROWB + ks * 32);
#pragma unroll
                for (int mt = 0; mt < 2; mt++)
#pragma unroll
                    for (int hf = 0; hf < 2; hf++) {
                        float* c = acc[mt][np * 2 + hf];
                        mma_f16(c, ah[mt], &bh[2 * hf]);
                        mma_f16(c, al[mt], &bh[2 * hf]);
                    }
            }
        }
        if (++slot >= NSTAGE) slot = 0;
    }

    // epilogue: bias + relu + fp16 hi/lo split
    const int mrow = m0 + wm * 32 + (lane >> 2);
    const int ncol0 = n0 + wn * 64 + 2 * (lane & 3);
#pragma unroll
    for (int mt = 0; mt < 2; mt++) {
#pragma unroll
        for (int nt = 0; nt < 8; nt++) {
            const int n = ncol0 + nt * 8;
            const float b0 = __ldg(bias + n), b1 = __ldg(bias + n + 1);
#pragma unroll
            for (int hf = 0; hf < 2; hf++) {
                const int m = mrow + mt * 16 + hf * 8;
                float y0 = fmaxf(acc[mt][nt][2 * hf] + b0, 0.0f);
                float y1 = fmaxf(acc[mt][nt][2 * hf + 1] + b1, 0.0f);
                uint32_t hi, lo;
                split_pack_h(y0, y1, hi, lo);
                *reinterpret_cast<uint32_t*>(o_hi + (size_t)m * Ddim + n) = hi;
                *reinterpret_cast<uint32_t*>(o_lo + (size_t)m * Ddim + n) = lo;
            }
        }
    }
}

// ---------------- output layer: N=1 dot ----------------
__global__ void out_kernel(float* __restrict__ out) {
    const int row = blockIdx.x * 8 + (threadIdx.x >> 5);
    const int lid = threadIdx.x & 31;
    const __half* hi = g_act_hi[1] + (size_t)row * Ddim;
    const __half* lo = g_act_lo[1] + (size_t)row * Ddim;
    float s = 0.0f;
    for (int j = lid; j < Ddim; j += 32)
        s += (__half2float(__ldg(hi + j)) + __half2float(__ldg(lo + j))) * __ldg(&g_wo[j]);
#pragma unroll
    for (int o = 16; o; o >>= 1) s += __shfl_xor_sync(0xFFFFFFFFu, s, o);
    if (lid == 0) out[row] = s + g_bo;
}

extern "C" void kernel_launch(void* const* d_in, const int* in_sizes, int n_in,
                              void* d_out, int out_size) {
    (void)in_sizes; (void)n_in; (void)out_size;
    prep_w_kernel<<<4096, 256>>>((const float4*)d_in[1], (const float4*)d_in[2],
                                 (const float4*)d_in[9]);
    prep_x_kernel<<<2048, 256>>>((const float4*)d_in[0]);
    prep_small_kernel<<<33, 256>>>((const float*)d_in[3], (const float*)d_in[4],
                                   (const float*)d_in[10],
                                   (const float*)d_in[5], (const float*)d_in[6],
                                   (const float*)d_in[11],
                                   (const float*)d_in[7], (const float*)d_in[8],
                                   (const float*)d_in[12]);
    cudaFuncSetAttribute(gemm_kernel, cudaFuncAttributeMaxDynamicSharedMemorySize, SMEM_TOTAL);
    dim3 grid(Bdim / BM, Ddim / BN);
    gemm_kernel<<<grid, GT, SMEM_TOTAL>>>(0, 0, 1);
    gemm_kernel<<<grid, GT, SMEM_TOTAL>>>(1, 1, 0);
    gemm_kernel<<<grid, GT, SMEM_TOTAL>>>(2, 0, 1);
    out_kernel<<<Bdim / 8, 256>>>((float*)d_out);
}